// round 1
// baseline (speedup 1.0000x reference)
#include <cuda_runtime.h>
#include <math_constants.h>

#define WIN   400
#define RNUM  64
#define BNUM  2
#define ANUM  3
#define KSEL  8
#define NV4   (WIN / 4)   // 100 float4 per window row

__global__ __launch_bounds__(256) void win_topk_kernel(
    const float* __restrict__ mixed,    // [B, S]
    const float* __restrict__ ref,      // [A, R, S]
    const float* __restrict__ weights,  // [K]
    float* __restrict__ out,            // [6000] scores ++ [48000] idx (as float)
    int S, int W, int write_idx)
{
    const int w    = blockIdx.x;
    const int a    = blockIdx.y;
    const int tid  = threadIdx.x;
    const int warp = tid >> 5;
    const int lane = tid & 31;

    __shared__ __align__(16) float sm_mixed[BNUM][WIN];
    __shared__ float sm_scores[BNUM][RNUM];
    __shared__ float sm_w[KSEL];

    const long base = (long)w * WIN;

    // Stage mixed tile (both batch rows) into shared, vectorized.
    {
        const float4* m4 = (const float4*)mixed;  // S % 4 == 0, base % 4 == 0
        float4* sm4 = (float4*)&sm_mixed[0][0];
        const int nv = BNUM * NV4;  // 200 float4
        for (int i = tid; i < nv; i += blockDim.x) {
            int b = i / NV4, v = i % NV4;
            sm4[b * NV4 + v] = m4[((long)b * S + base) / 4 + v];
        }
        if (tid < KSEL) sm_w[tid] = weights[tid];
    }
    __syncthreads();

    // Each warp computes windowed dot products for 8 ref rows (both batches).
    {
        const float4* sm0 = (const float4*)&sm_mixed[0][0];
        const float4* sm1 = (const float4*)&sm_mixed[1][0];
        const float* refa = ref + ((long)a * RNUM) * S + base;

        #pragma unroll
        for (int i = 0; i < RNUM / 8; i++) {
            const int r = warp * (RNUM / 8) + i;
            const float4* row4 = (const float4*)(refa + (long)r * S);

            float s0 = 0.f, s1 = 0.f;
            #pragma unroll
            for (int j = 0; j < 3; j++) {   // 96 vec4 covered by full warp
                int v = lane + j * 32;
                float4 rv = __ldg(&row4[v]);
                float4 m0 = sm0[v];
                float4 m1 = sm1[v];
                s0 = fmaf(rv.x, m0.x, s0); s0 = fmaf(rv.y, m0.y, s0);
                s0 = fmaf(rv.z, m0.z, s0); s0 = fmaf(rv.w, m0.w, s0);
                s1 = fmaf(rv.x, m1.x, s1); s1 = fmaf(rv.y, m1.y, s1);
                s1 = fmaf(rv.z, m1.z, s1); s1 = fmaf(rv.w, m1.w, s1);
            }
            if (lane < NV4 - 96) {          // tail: vec4 indices 96..99
                int v = 96 + lane;
                float4 rv = __ldg(&row4[v]);
                float4 m0 = sm0[v];
                float4 m1 = sm1[v];
                s0 = fmaf(rv.x, m0.x, s0); s0 = fmaf(rv.y, m0.y, s0);
                s0 = fmaf(rv.z, m0.z, s0); s0 = fmaf(rv.w, m0.w, s0);
                s1 = fmaf(rv.x, m1.x, s1); s1 = fmaf(rv.y, m1.y, s1);
                s1 = fmaf(rv.z, m1.z, s1); s1 = fmaf(rv.w, m1.w, s1);
            }
            // Warp reduction
            #pragma unroll
            for (int off = 16; off > 0; off >>= 1) {
                s0 += __shfl_down_sync(0xffffffffu, s0, off);
                s1 += __shfl_down_sync(0xffffffffu, s1, off);
            }
            if (lane == 0) {
                sm_scores[0][r] = s0 * (1.0f / WIN);
                sm_scores[1][r] = s1 * (1.0f / WIN);
            }
        }
    }
    __syncthreads();

    // Top-K (K=8) over 64 refs, warps 0 and 1 handle b=0/1.
    if (warp < BNUM) {
        const int b = warp;
        float v0 = sm_scores[b][lane];
        float v1 = sm_scores[b][lane + 32];
        float acc = 0.f;

        const long ow   = ((long)b * ANUM + a) * W + w;
        const long ibase = (long)6 * W + ow * KSEL;  // idx region after 6*W scores

        #pragma unroll
        for (int k = 0; k < KSEL; k++) {
            float bv; int bi;
            if (v0 >= v1) { bv = v0; bi = lane; }        // ties -> lower index
            else          { bv = v1; bi = lane + 32; }
            #pragma unroll
            for (int off = 16; off > 0; off >>= 1) {
                float ov = __shfl_xor_sync(0xffffffffu, bv, off);
                int   oi = __shfl_xor_sync(0xffffffffu, bi, off);
                if (ov > bv || (ov == bv && oi < bi)) { bv = ov; bi = oi; }
            }
            acc = fmaf(bv, sm_w[k], acc);
            if (write_idx && lane == 0) out[ibase + k] = (float)bi;
            if (bi == lane)      v0 = -CUDART_INF_F;
            if (bi == lane + 32) v1 = -CUDART_INF_F;
        }
        if (lane == 0) out[ow] = acc;
    }
}

extern "C" void kernel_launch(void* const* d_in, const int* in_sizes, int n_in,
                              void* d_out, int out_size) {
    const float* mixed   = (const float*)d_in[0];
    const float* ref     = (const float*)d_in[1];
    const float* weights = (const float*)d_in[2];
    float* out = (float*)d_out;

    const int S = in_sizes[0] / BNUM;      // 400000
    const int W = S / WIN;                 // 1000
    const int write_idx = (out_size >= BNUM * ANUM * W * (1 + KSEL)) ? 1 : 0;

    dim3 grid(W, ANUM);
    win_topk_kernel<<<grid, 256>>>(mixed, ref, weights, out, S, W, write_idx);
}